// round 9
// baseline (speedup 1.0000x reference)
#include <cuda_runtime.h>
#include <cstdint>

// Partitionable-threefry dropout (exact JAX match, rel_err = 0.0 confirmed):
//   bits[i] = fold(threefry2x32(key=(0,42), counter=(0,i))), fold = w0 ^ w1
//   keep    = bits < (7549747 << 9)
//   out[i]  = keep ? x[i] * (1/0.9) : 0,  cols [0,64) of each 4096-row -> 0
#define KS1 0x0000002Au
#define KS2 0x1BD11BF0u          // 0x1BD11BDA ^ 0 ^ 42

#define KEEP_CMP 0xE6666600u     // 7549747u << 9
#define DROP_SCALE ((float)(1.0 / 0.9))

__device__ __forceinline__ uint32_t rotl_shf(uint32_t x, int r) {
    return __funnelshift_l(x, x, r);   // SHF (alu pipe)
}

// Adds forced onto the fma pipe as IMAD (opaque multiplier `one` == 1).
__device__ __forceinline__ uint32_t fadd(uint32_t a, uint32_t b, uint32_t one) {
    uint32_t r;
    asm("mad.lo.u32 %0, %1, %2, %3;" : "=r"(r) : "r"(b), "r"(one), "r"(a));
    return r;
}
template <uint32_t C>
__device__ __forceinline__ uint32_t faddc(uint32_t a, uint32_t one) {
    uint32_t r;
    asm("mad.lo.u32 %0, %1, %2, %3;" : "=r"(r) : "r"(a), "r"(one), "n"(C));
    return r;
}

// Rotate via wide multiply on the fma pipe:
//   t = x * 2^R (IMAD.WIDE): t.lo = x<<R, t.hi = x>>(32-R), disjoint bits.
//   (t.lo | t.hi) ^ x0 fuses into ONE LOP3 (alu).
// SHF round: 2 alu + 1 fma.  Wide round: 1 alu + 2 fma.
template <int R>
__device__ __forceinline__ uint32_t rot_xor_wide(uint32_t x1, uint32_t x0) {
    uint32_t lo, hi;
    asm("{\n\t"
        ".reg .u64 t;\n\t"
        "mul.wide.u32 t, %2, %3;\n\t"
        "mov.b64 {%0, %1}, t;\n\t"
        "}"
        : "=r"(lo), "=r"(hi) : "r"(x1), "n"(1u << R));
    return (lo | hi) ^ x0;
}

// Full threefry2x32 block, c0 = 0, c1 = i, key (0,42); returns w0 ^ w1.
// 10 SHF rounds + 10 wide rounds (alternating), x0 key-injections merged
// into the following round's add as IADD3 (plain C++ 3-way add).
// Per element: alu ~= 36, fma ~= 34, issue ~= 72 -> balanced/issue-bound.
__device__ __forceinline__ uint32_t threefry_fold(uint32_t i, uint32_t one) {
    uint32_t x1 = faddc<KS1>(i, one);       // x1 = i + 42
    uint32_t x0 = x1;                       // round-1 add folds (x0 was 0)
    x1 = rot_xor_wide<13>(x1, x0);                              // r1  W

    x0 = fadd(x0, x1, one); x1 = rotl_shf(x1, 15) ^ x0;         // r2  S
    x0 = fadd(x0, x1, one); x1 = rot_xor_wide<26>(x1, x0);      // r3  W
    x0 = fadd(x0, x1, one); x1 = rotl_shf(x1,  6) ^ x0;         // r4  S
    x1 = faddc<KS2 + 1u>(x1, one);

    x0 = x0 + KS1 + x1;     x1 = rot_xor_wide<17>(x1, x0);      // r5  W (IADD3 merge)
    x0 = fadd(x0, x1, one); x1 = rotl_shf(x1, 29) ^ x0;         // r6  S
    x0 = fadd(x0, x1, one); x1 = rot_xor_wide<16>(x1, x0);      // r7  W
    x0 = fadd(x0, x1, one); x1 = rotl_shf(x1, 24) ^ x0;         // r8  S
    x1 = faddc<2u>(x1, one);

    x0 = x0 + KS2 + x1;     x1 = rot_xor_wide<13>(x1, x0);      // r9  W (IADD3 merge)
    x0 = fadd(x0, x1, one); x1 = rotl_shf(x1, 15) ^ x0;         // r10 S
    x0 = fadd(x0, x1, one); x1 = rot_xor_wide<26>(x1, x0);      // r11 W
    x0 = fadd(x0, x1, one); x1 = rotl_shf(x1,  6) ^ x0;         // r12 S
    /* x0 += KS0 == 0: skipped */ x1 = faddc<KS1 + 3u>(x1, one);

    x0 = fadd(x0, x1, one); x1 = rot_xor_wide<17>(x1, x0);      // r13 W
    x0 = fadd(x0, x1, one); x1 = rotl_shf(x1, 29) ^ x0;         // r14 S
    x0 = fadd(x0, x1, one); x1 = rot_xor_wide<16>(x1, x0);      // r15 W
    x0 = fadd(x0, x1, one); x1 = rotl_shf(x1, 24) ^ x0;         // r16 S
    x1 = faddc<KS2 + 4u>(x1, one);

    x0 = x0 + KS1 + x1;     x1 = rot_xor_wide<13>(x1, x0);      // r17 W (IADD3 merge)
    x0 = fadd(x0, x1, one); x1 = rotl_shf(x1, 15) ^ x0;         // r18 S
    x0 = fadd(x0, x1, one); x1 = rot_xor_wide<26>(x1, x0);      // r19 W
    x0 = fadd(x0, x1, one); x1 = rotl_shf(x1,  6) ^ x0;         // r20 S
    x0 = faddc<KS2>(x0, one); x1 = faddc<5u>(x1, one);

    return x0 ^ x1;
}

// 8 consecutive elements per thread: two float4 loads/stores, 8 independent
// threefry chains for ILP. base is 8-aligned and 64 % 8 == 0, so the
// column-kill test (i & 4095) < 64 is uniform across the group.
__global__ void __launch_bounds__(256, 4)
dropout_threefry_part_kernel(const float* __restrict__ x,
                             float* __restrict__ out,
                             uint32_t one) {
    uint32_t base = (blockIdx.x * blockDim.x + threadIdx.x) * 8u;

    const float4 a = *reinterpret_cast<const float4*>(x + base);
    const float4 b = *reinterpret_cast<const float4*>(x + base + 4u);

    const float scale = ((base & 4095u) < 64u) ? 0.0f : DROP_SCALE;

    uint32_t bits[8];
#pragma unroll
    for (int j = 0; j < 8; ++j) {
        bits[j] = threefry_fold(base + (uint32_t)j, one);
    }

    // Predicated-multiply tail: ISETP + @p FMUL.
    float va[8] = {a.x, a.y, a.z, a.w, b.x, b.y, b.z, b.w};
    float r[8];
#pragma unroll
    for (int j = 0; j < 8; ++j) {
        float v = 0.0f;
        if (bits[j] < KEEP_CMP) v = va[j] * scale;
        r[j] = v;
    }

    float4 ra, rb;
    ra.x = r[0]; ra.y = r[1]; ra.z = r[2]; ra.w = r[3];
    rb.x = r[4]; rb.y = r[5]; rb.z = r[6]; rb.w = r[7];

    *reinterpret_cast<float4*>(out + base) = ra;
    *reinterpret_cast<float4*>(out + base + 4u) = rb;
}

extern "C" void kernel_launch(void* const* d_in, const int* in_sizes, int n_in,
                              void* d_out, int out_size) {
    const float* x = (const float*)d_in[0];
    float* out = (float*)d_out;

    const uint32_t n = (uint32_t)out_size;   // 16384 * 4096 = 2^26
    const int threads = 256;
    const uint32_t elems_per_block = threads * 8u;
    const int blocks = (int)((n + elems_per_block - 1) / elems_per_block);

    dropout_threefry_part_kernel<<<blocks, threads>>>(x, out, 1u);
}

// round 10
// speedup vs baseline: 1.0548x; 1.0548x over previous
#include <cuda_runtime.h>
#include <cstdint>

// Partitionable-threefry dropout (exact JAX match, rel_err = 0.0 confirmed):
//   bits[i] = fold(threefry2x32(key=(0,42), counter=(0,i))), fold = w0 ^ w1
//   keep    = bits < (7549747 << 9)
//   out[i]  = keep ? x[i] * (1/0.9) : 0,  cols [0,64) of each 4096-row -> 0
#define KS1 0x0000002Au
#define KS2 0x1BD11BF0u          // 0x1BD11BDA ^ 0 ^ 42

#define KEEP_CMP 0xE6666600u     // 7549747u << 9
#define DROP_SCALE ((float)(1.0 / 0.9))

__device__ __forceinline__ uint32_t rotl_shf(uint32_t x, int r) {
    return __funnelshift_l(x, x, r);   // SHF (alu pipe)
}

// Adds forced onto the fma pipe as IMAD (opaque multiplier `one` == 1).
__device__ __forceinline__ uint32_t fadd(uint32_t a, uint32_t b, uint32_t one) {
    uint32_t r;
    asm("mad.lo.u32 %0, %1, %2, %3;" : "=r"(r) : "r"(b), "r"(one), "r"(a));
    return r;
}
template <uint32_t C>
__device__ __forceinline__ uint32_t faddc(uint32_t a, uint32_t one) {
    uint32_t r;
    asm("mad.lo.u32 %0, %1, %2, %3;" : "=r"(r) : "r"(a), "r"(one), "n"(C));
    return r;
}

// Rotate on the fma pipe WITHOUT 64-bit pairs:
//   p = 2^r (runtime register, not const-foldable)
//   lo = x * p (IMAD, low 32)   = x << r
//   hi = umulhi(x, p) (IMAD.HI) = x >> (32-r)
//   (lo | hi) ^ x0 fuses into ONE 3-input LOP3.
// Round cost: 1 alu + 3 fma (vs 2 alu + 1 fma for the SHF form).
__device__ __forceinline__ uint32_t rot_xor_mul(uint32_t x1, uint32_t x0, uint32_t p) {
    uint32_t lo;
    asm("mul.lo.u32 %0, %1, %2;" : "=r"(lo) : "r"(x1), "r"(p));
    uint32_t hi = __umulhi(x1, p);
    return (lo | hi) ^ x0;
}

// Full threefry2x32 block, c0 = 0, c1 = i, key (0,42); returns w0 ^ w1.
// 16 SHF rounds + 4 mul-pair rounds (r1, r6, r11, r16):
// alu ~= 39/elem, fma ~= 39/elem, issue ~= 78 -> all three resources balanced.
__device__ __forceinline__ uint32_t threefry_fold(uint32_t i, uint32_t one,
                                                  uint32_t p13, uint32_t p29,
                                                  uint32_t p26, uint32_t p24) {
    uint32_t x1 = faddc<KS1>(i, one);       // x1 = i + 42
    uint32_t x0 = x1;                       // round-1 add folds (x0 was 0)
    x1 = rot_xor_mul(x1, x0, p13);                              // r1  M

    x0 = fadd(x0, x1, one); x1 = rotl_shf(x1, 15) ^ x0;         // r2
    x0 = fadd(x0, x1, one); x1 = rotl_shf(x1, 26) ^ x0;         // r3
    x0 = fadd(x0, x1, one); x1 = rotl_shf(x1,  6) ^ x0;         // r4
    x0 = faddc<KS1>(x0, one); x1 = faddc<KS2 + 1u>(x1, one);

    x0 = fadd(x0, x1, one); x1 = rotl_shf(x1, 17) ^ x0;         // r5
    x0 = fadd(x0, x1, one); x1 = rot_xor_mul(x1, x0, p29);      // r6  M
    x0 = fadd(x0, x1, one); x1 = rotl_shf(x1, 16) ^ x0;         // r7
    x0 = fadd(x0, x1, one); x1 = rotl_shf(x1, 24) ^ x0;         // r8
    x0 = faddc<KS2>(x0, one); x1 = faddc<2u>(x1, one);

    x0 = fadd(x0, x1, one); x1 = rotl_shf(x1, 13) ^ x0;         // r9
    x0 = fadd(x0, x1, one); x1 = rotl_shf(x1, 15) ^ x0;         // r10
    x0 = fadd(x0, x1, one); x1 = rot_xor_mul(x1, x0, p26);      // r11 M
    x0 = fadd(x0, x1, one); x1 = rotl_shf(x1,  6) ^ x0;         // r12
    /* x0 += KS0 == 0: skipped */ x1 = faddc<KS1 + 3u>(x1, one);

    x0 = fadd(x0, x1, one); x1 = rotl_shf(x1, 17) ^ x0;         // r13
    x0 = fadd(x0, x1, one); x1 = rotl_shf(x1, 29) ^ x0;         // r14
    x0 = fadd(x0, x1, one); x1 = rotl_shf(x1, 16) ^ x0;         // r15
    x0 = fadd(x0, x1, one); x1 = rot_xor_mul(x1, x0, p24);      // r16 M
    x0 = faddc<KS1>(x0, one); x1 = faddc<KS2 + 4u>(x1, one);

    x0 = fadd(x0, x1, one); x1 = rotl_shf(x1, 13) ^ x0;         // r17
    x0 = fadd(x0, x1, one); x1 = rotl_shf(x1, 15) ^ x0;         // r18
    x0 = fadd(x0, x1, one); x1 = rotl_shf(x1, 26) ^ x0;         // r19
    x0 = fadd(x0, x1, one); x1 = rotl_shf(x1,  6) ^ x0;         // r20
    x0 = faddc<KS2>(x0, one); x1 = faddc<5u>(x1, one);

    return x0 ^ x1;
}

// 8 consecutive elements per thread: two float4 loads/stores, 8 independent
// threefry chains for ILP. base is 8-aligned and 64 % 8 == 0, so the
// column-kill test (i & 4095) < 64 is uniform across the group.
__global__ void __launch_bounds__(256, 6)
dropout_threefry_part_kernel(const float* __restrict__ x,
                             float* __restrict__ out,
                             uint32_t one) {
    // Runtime powers of two (opaque to ptxas -> multiplies stay IMAD/IMAD.HI).
    const uint32_t p13 = one << 13;
    const uint32_t p29 = one << 29;
    const uint32_t p26 = one << 26;
    const uint32_t p24 = one << 24;

    uint32_t base = (blockIdx.x * blockDim.x + threadIdx.x) * 8u;

    const float4 a = *reinterpret_cast<const float4*>(x + base);
    const float4 b = *reinterpret_cast<const float4*>(x + base + 4u);

    const float scale = ((base & 4095u) < 64u) ? 0.0f : DROP_SCALE;

    uint32_t bits[8];
#pragma unroll
    for (int j = 0; j < 8; ++j) {
        bits[j] = threefry_fold(base + (uint32_t)j, one, p13, p29, p26, p24);
    }

    // Predicated-multiply tail: ISETP + @p FMUL.
    float va[8] = {a.x, a.y, a.z, a.w, b.x, b.y, b.z, b.w};
    float r[8];
#pragma unroll
    for (int j = 0; j < 8; ++j) {
        float v = 0.0f;
        if (bits[j] < KEEP_CMP) v = va[j] * scale;
        r[j] = v;
    }

    float4 ra, rb;
    ra.x = r[0]; ra.y = r[1]; ra.z = r[2]; ra.w = r[3];
    rb.x = r[4]; rb.y = r[5]; rb.z = r[6]; rb.w = r[7];

    *reinterpret_cast<float4*>(out + base) = ra;
    *reinterpret_cast<float4*>(out + base + 4u) = rb;
}

extern "C" void kernel_launch(void* const* d_in, const int* in_sizes, int n_in,
                              void* d_out, int out_size) {
    const float* x = (const float*)d_in[0];
    float* out = (float*)d_out;

    const uint32_t n = (uint32_t)out_size;   // 16384 * 4096 = 2^26
    const int threads = 256;
    const uint32_t elems_per_block = threads * 8u;
    const int blocks = (int)((n + elems_per_block - 1) / elems_per_block);

    dropout_threefry_part_kernel<<<blocks, threads>>>(x, out, 1u);
}